// round 4
// baseline (speedup 1.0000x reference)
#include <cuda_runtime.h>

// Dynamics_individual (MAK), N=8192, B=R=F=1
// d_in[0]=t (unused), d_in[1]=x [N], d_in[2]=A [N,N]
// d_out = [ f_self (N) | f_nbr (N*N) ], f_self[i]=1-x[i], f_nbr[i][j]=-x[i]*A[i][j]*x[j]
//
// 256-bit global ld/st (sm_100a+): each "oct" = 8 floats = 32 bytes.
// Total octs = 8192*8192/8 = 8,388,608. Block covers 512 octs (half a row),
// so row index i is uniform per block. 16384 blocks x 256 threads.

#define NDIM 8192u
#define TPB 256u
#define OCTS_PER_ROW 1024u       // 8192/8
#define OCTS_PER_BLOCK 512u      // 2 octs per thread

__device__ __forceinline__ void ldg256_cs(const float* p, float v[8]) {
    asm volatile(
        "ld.global.cs.v8.f32 {%0,%1,%2,%3,%4,%5,%6,%7}, [%8];"
        : "=f"(v[0]), "=f"(v[1]), "=f"(v[2]), "=f"(v[3]),
          "=f"(v[4]), "=f"(v[5]), "=f"(v[6]), "=f"(v[7])
        : "l"(p));
}

__device__ __forceinline__ void stg256_cs(float* p, const float v[8]) {
    asm volatile(
        "st.global.cs.v8.f32 [%0], {%1,%2,%3,%4,%5,%6,%7,%8};"
        :: "l"(p),
           "f"(v[0]), "f"(v[1]), "f"(v[2]), "f"(v[3]),
           "f"(v[4]), "f"(v[5]), "f"(v[6]), "f"(v[7])
        : "memory");
}

__global__ void __launch_bounds__(256) dyn_mak_kernel(
    const float* __restrict__ x,
    const float* __restrict__ A,
    float* __restrict__ out)
{
    const unsigned o0 = blockIdx.x * OCTS_PER_BLOCK + threadIdx.x;
    const unsigned o1 = o0 + TPB;

    // Row is uniform per block (block spans half a row).
    const unsigned i = blockIdx.x >> 1;
    const float s = -__ldg(&x[i]);

    // Front-batched: 2 x 256-bit loads in flight per thread (16 lines/warp/ld).
    float a0[8], a1[8];
    ldg256_cs(A + (size_t)o0 * 8u, a0);
    ldg256_cs(A + (size_t)o1 * 8u, a1);

    const unsigned j0 = (o0 & (OCTS_PER_ROW - 1u)) * 8u;
    const unsigned j1 = (o1 & (OCTS_PER_ROW - 1u)) * 8u;

    float* __restrict__ fnbr = out + NDIM;

    float r0[8], r1[8];
#pragma unroll
    for (int k = 0; k < 8; k++) r0[k] = s * a0[k] * __ldg(&x[j0 + k]);
#pragma unroll
    for (int k = 0; k < 8; k++) r1[k] = s * a1[k] * __ldg(&x[j1 + k]);

    stg256_cs(fnbr + (size_t)o0 * 8u, r0);
    stg256_cs(fnbr + (size_t)o1 * 8u, r1);

    // f_self occupies octs 0..1023 of x-space: handled by blocks 0 and 1.
    if (blockIdx.x < 2) {
        const unsigned so0 = blockIdx.x * OCTS_PER_BLOCK + threadIdx.x;
        const unsigned so1 = so0 + TPB;
        float fs0[8], fs1[8];
#pragma unroll
        for (int k = 0; k < 8; k++) fs0[k] = 1.0f - __ldg(&x[so0 * 8u + k]);
#pragma unroll
        for (int k = 0; k < 8; k++) fs1[k] = 1.0f - __ldg(&x[so1 * 8u + k]);
        stg256_cs(out + (size_t)so0 * 8u, fs0);
        stg256_cs(out + (size_t)so1 * 8u, fs1);
    }
}

extern "C" void kernel_launch(void* const* d_in, const int* in_sizes, int n_in,
                              void* d_out, int out_size)
{
    (void)in_sizes; (void)n_in; (void)out_size;
    const float* x = (const float*)d_in[1];
    const float* A = (const float*)d_in[2];
    float* out = (float*)d_out;

    const unsigned total_octs = NDIM * NDIM / 8u;            // 8,388,608
    const unsigned blocks = total_octs / OCTS_PER_BLOCK;     // 16,384

    dyn_mak_kernel<<<blocks, TPB>>>(x, A, out);
}

// round 5
// speedup vs baseline: 1.0504x; 1.0504x over previous
#include <cuda_runtime.h>

// Dynamics_individual (MAK), N=8192, B=R=F=1
// d_in[0]=t (unused), d_in[1]=x [N], d_in[2]=A [N,N]
// d_out = [ f_self (N) | f_nbr (N*N) ], f_self[i]=1-x[i], f_nbr[i][j]=-x[i]*A[i][j]*x[j]
//
// One block == one full row (2048 float4 quads). TPB=512, 4 quads/thread,
// front-batched LDG.128 (MLP=4), streaming hints both directions.

#define NDIM 8192u
#define QUADS_PER_ROW 2048u      // N/4
#define TPB 512u
#define QPT 4u                   // quads per thread

__global__ void __launch_bounds__(512) dyn_mak_kernel(
    const float* __restrict__ x,
    const float* __restrict__ A,
    float* __restrict__ out)
{
    const unsigned i = blockIdx.x;                       // row, uniform per block
    const unsigned base = i * QUADS_PER_ROW + threadIdx.x;

    const float4* __restrict__ A4 = reinterpret_cast<const float4*>(A);
    const float4* __restrict__ x4 = reinterpret_cast<const float4*>(x);
    float4* __restrict__ fnbr = reinterpret_cast<float4*>(out + NDIM);

    const float s = -__ldg(&x[i]);

    // Front-batched: 4 independent LDG.128 in flight per thread.
    float4 a[QPT];
#pragma unroll
    for (int k = 0; k < (int)QPT; k++)
        a[k] = __ldcs(&A4[base + (unsigned)k * TPB]);

#pragma unroll
    for (int k = 0; k < (int)QPT; k++) {
        const unsigned j4 = threadIdx.x + (unsigned)k * TPB;  // col quad in row
        const float4 xj = x4[j4];                             // L1-resident 8 KB
        float4 r;
        r.x = s * a[k].x * xj.x;
        r.y = s * a[k].y * xj.y;
        r.z = s * a[k].z * xj.z;
        r.w = s * a[k].w * xj.w;
        __stcs(&fnbr[base + (unsigned)k * TPB], r);
    }

    // f_self = 1 - x : 2048 quads, exactly block 0's per-row quad range.
    if (i == 0) {
#pragma unroll
        for (int k = 0; k < (int)QPT; k++) {
            const unsigned q = threadIdx.x + (unsigned)k * TPB;
            const float4 xv = x4[q];
            float4 fs;
            fs.x = 1.0f - xv.x;
            fs.y = 1.0f - xv.y;
            fs.z = 1.0f - xv.z;
            fs.w = 1.0f - xv.w;
            reinterpret_cast<float4*>(out)[q] = fs;
        }
    }
}

extern "C" void kernel_launch(void* const* d_in, const int* in_sizes, int n_in,
                              void* d_out, int out_size)
{
    (void)in_sizes; (void)n_in; (void)out_size;
    const float* x = (const float*)d_in[1];
    const float* A = (const float*)d_in[2];
    float* out = (float*)d_out;

    dyn_mak_kernel<<<NDIM, TPB>>>(x, A, out);   // 8192 blocks, one row each
}